// round 6
// baseline (speedup 1.0000x reference)
#include <cuda_runtime.h>
#include <cuda_fp16.h>

// Problem constants (fixed by the reference setup_inputs)
constexpr int N_USERS = 200000;
constexpr int N_ITEMS = 100000;
constexpr int N_NODES = N_USERS + N_ITEMS;   // 300000
constexpr int N_EDGES = 2000000;
constexpr int N_IDX   = 16384;
constexpr int DH      = 8;                   // 64 halves = 8 uint4 (16B) per row
constexpr int N_SEL   = 2 * N_IDX;           // sampled-node list (with dups)
constexpr int LIST_MAX = 262144;             // static bound on layer-2 active rows

constexpr int SCAN_B  = 1024;
constexpr int NBLK    = (N_NODES + SCAN_B - 1) / SCAN_B;  // 293

// Allocation-free scratch (__device__ globals; zero-initialized at load)
__device__ uint4  g_bufA[(size_t)N_NODES * DH];   // 38.4 MB (fp16 rows)
__device__ uint4  g_bufB[(size_t)N_NODES * DH];   // 38.4 MB
__device__ int    g_cnt[N_NODES];                 // invariant: zero at launch entry
__device__ int    g_rowptr[N_NODES + 1];
__device__ int    g_cursor[N_NODES];
__device__ int    g_bsum[NBLK];
__device__ float2 g_edge[N_EDGES];                // {val, col-as-float-bits}, row-sorted
__device__ int    g_sel[N_SEL];                   // sampled nodes (dups ok)
__device__ int    g_flag[N_NODES];                // sel flags   (invariant: zero)
__device__ int    g_flag2[N_NODES];               // nbr flags   (invariant: zero)
__device__ int    g_list[LIST_MAX];               // layer-2 active rows
__device__ int    g_nlist;

__device__ __forceinline__ uint4 pack8(const float* a) {
    uint4 r;
    half2 h0 = __floats2half2_rn(a[0], a[1]);
    half2 h1 = __floats2half2_rn(a[2], a[3]);
    half2 h2 = __floats2half2_rn(a[4], a[5]);
    half2 h3 = __floats2half2_rn(a[6], a[7]);
    r.x = *(const unsigned*)&h0; r.y = *(const unsigned*)&h1;
    r.z = *(const unsigned*)&h2; r.w = *(const unsigned*)&h3;
    return r;
}

__device__ __forceinline__ void unpack8(uint4 v, float* a) {
    float2 f0 = __half22float2(*(const half2*)&v.x);
    float2 f1 = __half22float2(*(const half2*)&v.y);
    float2 f2 = __half22float2(*(const half2*)&v.z);
    float2 f3 = __half22float2(*(const half2*)&v.w);
    a[0] = f0.x; a[1] = f0.y; a[2] = f1.x; a[3] = f1.y;
    a[4] = f2.x; a[5] = f2.y; a[6] = f3.x; a[7] = f3.y;
}

// ---------------------------------------------------------------------------
// prep: (a) bufA = fp16(concat(uw, iw)); (b) edge-row histogram;
// (c) sel list + sel flags; (d) exact layer-0 output gather from fp32 weights.
__global__ void prep_kernel(const float4* __restrict__ uw,
                            const float4* __restrict__ iw,
                            const int* __restrict__ rows,
                            const int* __restrict__ uidx,
                            const int* __restrict__ iidx,
                            float4* __restrict__ out) {
    int t = blockIdx.x * blockDim.x + threadIdx.x;

    if (t < N_NODES * DH) {
        const float4* src = (t < N_USERS * DH) ? uw : iw;
        int idx2 = (t < N_USERS * DH) ? (t * 2) : ((t - N_USERS * DH) * 2);
        float4 a = __ldg(src + idx2);
        float4 b = __ldg(src + idx2 + 1);
        float f[8] = {a.x, a.y, a.z, a.w, b.x, b.y, b.z, b.w};
        g_bufA[t] = pack8(f);
    }
    if (t < N_EDGES) atomicAdd(&g_cnt[__ldg(rows + t)], 1);
    if (t < N_SEL) {
        int node = (t < N_IDX) ? __ldg(uidx + t)
                               : (N_USERS + __ldg(iidx + (t - N_IDX)));
        g_sel[t] = node;
        g_flag[node] = 1;                 // benign race
    }
    if (t == 0) g_nlist = 0;
    if (t < N_SEL * 16) {
        int row = t >> 4;
        int c   = t & 15;
        const float4* src;
        int node;
        if (row < N_IDX) { src = uw; node = __ldg(uidx + row); }
        else             { src = iw; node = __ldg(iidx + (row - N_IDX)); }
        float4 x = __ldg(src + (unsigned)node * 16 + c);
        out[t] = make_float4(0.25f * x.x, 0.25f * x.y, 0.25f * x.z, 0.25f * x.w);
    }
}

// mark neighbor cols of sel rows (raw COO pass; benign races)
__global__ void mark_nbr_kernel(const int* __restrict__ rows,
                                const int* __restrict__ cols) {
    int e = blockIdx.x * blockDim.x + threadIdx.x;
    if (e >= N_EDGES) return;
    if (g_flag[__ldg(rows + e)]) g_flag2[__ldg(cols + e)] = 1;
}

// compact flag|flag2 -> g_list; resets both flag arrays (per-launch invariant)
__global__ void compact_kernel() {
    int t = blockIdx.x * blockDim.x + threadIdx.x;
    if (t >= N_NODES) return;
    int f = g_flag[t] | g_flag2[t];
    g_flag[t] = 0;
    g_flag2[t] = 0;
    unsigned ball = __ballot_sync(0xffffffffu, f);
    int lane = threadIdx.x & 31;
    int base = 0;
    if (lane == 0 && ball) base = atomicAdd(&g_nlist, __popc(ball));
    base = __shfl_sync(0xffffffffu, base, 0);
    if (f) g_list[base + __popc(ball & ((1u << lane) - 1u))] = t;
}

// ---------------------------------------------------------------------------
// shfl-based block scans (exclusive) over g_cnt -> g_rowptr.
// scan_blocks also RESETS g_cnt to 0 (launch invariant for next call).
__global__ void scan_blocks_kernel() {
    __shared__ int wsum[32];
    int i = blockIdx.x * SCAN_B + threadIdx.x;
    int v = (i < N_NODES) ? g_cnt[i] : 0;
    if (i < N_NODES) g_cnt[i] = 0;
    int lane = threadIdx.x & 31, wid = threadIdx.x >> 5;
    int s = v;
    #pragma unroll
    for (int off = 1; off < 32; off <<= 1) {
        int n = __shfl_up_sync(0xffffffffu, s, off);
        if (lane >= off) s += n;
    }
    if (lane == 31) wsum[wid] = s;
    __syncthreads();
    if (wid == 0) {
        int ws = wsum[lane];
        #pragma unroll
        for (int off = 1; off < 32; off <<= 1) {
            int n = __shfl_up_sync(0xffffffffu, ws, off);
            if (lane >= off) ws += n;
        }
        wsum[lane] = ws;
    }
    __syncthreads();
    int incl = s + ((wid > 0) ? wsum[wid - 1] : 0);
    if (i < N_NODES) g_rowptr[i] = incl - v;
    if (threadIdx.x == SCAN_B - 1) g_bsum[blockIdx.x] = incl;
}

__global__ void scan_bsums_kernel() {   // 512 threads, NBLK=293
    __shared__ int wsum[16];
    int lane = threadIdx.x & 31, wid = threadIdx.x >> 5;
    int v = (threadIdx.x < NBLK) ? g_bsum[threadIdx.x] : 0;
    int s = v;
    #pragma unroll
    for (int off = 1; off < 32; off <<= 1) {
        int n = __shfl_up_sync(0xffffffffu, s, off);
        if (lane >= off) s += n;
    }
    if (lane == 31) wsum[wid] = s;
    __syncthreads();
    if (wid == 0 && lane < 16) {
        int ws = wsum[lane];
        #pragma unroll
        for (int off = 1; off < 16; off <<= 1) {
            int n = __shfl_up_sync(0x0000ffffu, ws, off);
            if (lane >= off) ws += n;
        }
        wsum[lane] = ws;
    }
    __syncthreads();
    int incl = s + ((wid > 0) ? wsum[wid - 1] : 0);
    if (threadIdx.x < NBLK) g_bsum[threadIdx.x] = incl - v;
}

__global__ void scan_add_kernel() {
    int i = blockIdx.x * SCAN_B + threadIdx.x;
    if (i < N_NODES) {
        int r = g_rowptr[i] + g_bsum[blockIdx.x];
        g_rowptr[i] = r;
        g_cursor[i] = r;
    }
    if (i == 0) g_rowptr[N_NODES] = N_EDGES;
}

// scatter edges into row-sorted packed array; 4 edges per thread (ILP)
__global__ void scatter_kernel(const float4* __restrict__ vals4,
                               const int4*   __restrict__ rows4,
                               const int4*   __restrict__ cols4) {
    int q = blockIdx.x * blockDim.x + threadIdx.x;
    if (q >= N_EDGES / 4) return;
    int4   r = __ldg(rows4 + q);
    int4   c = __ldg(cols4 + q);
    float4 v = __ldg(vals4 + q);
    int p0 = atomicAdd(&g_cursor[r.x], 1);
    int p1 = atomicAdd(&g_cursor[r.y], 1);
    int p2 = atomicAdd(&g_cursor[r.z], 1);
    int p3 = atomicAdd(&g_cursor[r.w], 1);
    g_edge[p0] = make_float2(v.x, __int_as_float(c.x));
    g_edge[p1] = make_float2(v.y, __int_as_float(c.y));
    g_edge[p2] = make_float2(v.z, __int_as_float(c.z));
    g_edge[p3] = make_float2(v.w, __int_as_float(c.w));
}

// ---------------------------------------------------------------------------
// Row body: direct per-thread CSR loop, chunk-4 with zero-padding.
__device__ __forceinline__ void spmm_row(const uint4* __restrict__ cur,
                                         uint4* __restrict__ nxt,
                                         int row, int c) {
    int beg = __ldg(&g_rowptr[row]);
    int end = __ldg(&g_rowptr[row + 1]);

    float acc[8] = {0.f, 0.f, 0.f, 0.f, 0.f, 0.f, 0.f, 0.f};
    for (int base = beg; base < end; base += 4) {
        float2 ev[4];
        #pragma unroll
        for (int k = 0; k < 4; k++) {
            int idx = base + k;
            ev[k] = (idx < end) ? __ldg((const float2*)g_edge + idx)
                                : make_float2(0.f, __int_as_float(0));
        }
        uint4 p[4];
        #pragma unroll
        for (int k = 0; k < 4; k++)
            p[k] = __ldg(cur + (unsigned)__float_as_int(ev[k].y) * DH + c);
        #pragma unroll
        for (int k = 0; k < 4; k++) {
            float x[8];
            unpack8(p[k], x);
            #pragma unroll
            for (int j = 0; j < 8; j++) acc[j] += ev[k].x * x[j];
        }
    }
    nxt[(unsigned)row * DH + c] = pack8(acc);
}

// Fused gather tail: out += 0.25 * buf16[sampled]  (8 threads/sampled row)
__device__ __forceinline__ void gather_body(const uint4* __restrict__ buf,
                                            float4* __restrict__ out, int t) {
    int row = t >> 3;
    int c   = t & 7;
    int node = g_sel[row];
    float x[8];
    unpack8(__ldg(buf + (unsigned)node * DH + c), x);
    float4* o = out + (unsigned)row * 16 + c * 2;
    float4 p0 = o[0], p1 = o[1];
    o[0] = make_float4(p0.x + 0.25f * x[0], p0.y + 0.25f * x[1],
                       p0.z + 0.25f * x[2], p0.w + 0.25f * x[3]);
    o[1] = make_float4(p1.x + 0.25f * x[4], p1.y + 0.25f * x[5],
                       p1.z + 0.25f * x[6], p1.w + 0.25f * x[7]);
}

constexpr int SPMM_BLOCKS   = (N_NODES * DH) / 256;          // 9375
constexpr int GATHER_BLOCKS = (N_SEL * DH) / 256;            // 1024
constexpr int SEL_BLOCKS    = (N_SEL * DH) / 256;            // 1024
constexpr int LIST_BLOCKS   = (LIST_MAX * DH) / 256;         // 8192

// Full SpMM over all rows. DIR=0: A->B, DIR=1: B->A.
template <int DIR>
__global__ void spmm_csr_kernel() {
    const uint4* __restrict__ cur = DIR ? g_bufB : g_bufA;
    uint4*       __restrict__ nxt = DIR ? g_bufA : g_bufB;
    int t = blockIdx.x * blockDim.x + threadIdx.x;
    spmm_row(cur, nxt, t >> 3, t & 7);
}

// SpMM over g_list rows (layer 2) + fused gather of previous layer.
template <int DIR, int GPREV>
__global__ void spmm_list_kernel(float4* __restrict__ out) {
    const uint4* __restrict__ cur = DIR ? g_bufB : g_bufA;
    uint4*       __restrict__ nxt = DIR ? g_bufA : g_bufB;
    int b = blockIdx.x;
    if (b < LIST_BLOCKS) {
        int t = b * blockDim.x + threadIdx.x;
        int ridx = t >> 3;
        if (ridx < g_nlist) spmm_row(cur, nxt, g_list[ridx], t & 7);
    } else {
        int t = (b - LIST_BLOCKS) * blockDim.x + threadIdx.x;
        gather_body(GPREV ? g_bufB : g_bufA, out, t);
    }
}

// SpMM over sampled rows (layer 3; dups benign) + fused gather.
template <int DIR, int GPREV>
__global__ void spmm_sel_kernel(float4* __restrict__ out) {
    const uint4* __restrict__ cur = DIR ? g_bufB : g_bufA;
    uint4*       __restrict__ nxt = DIR ? g_bufA : g_bufB;
    int b = blockIdx.x;
    if (b < SEL_BLOCKS) {
        int t = b * blockDim.x + threadIdx.x;
        spmm_row(cur, nxt, g_sel[t >> 3], t & 7);
    } else {
        int t = (b - SEL_BLOCKS) * blockDim.x + threadIdx.x;
        gather_body(GPREV ? g_bufB : g_bufA, out, t);
    }
}

// Final standalone gather (layer 3 result)
template <int W>
__global__ void gather_kernel(float4* __restrict__ out) {
    int t = blockIdx.x * blockDim.x + threadIdx.x;
    gather_body(W ? g_bufB : g_bufA, out, t);
}

extern "C" void kernel_launch(void* const* d_in, const int* in_sizes, int n_in,
                              void* d_out, int out_size) {
    const float4* uw   = (const float4*)d_in[0];
    const float4* iw   = (const float4*)d_in[1];
    const float*  vals = (const float*)d_in[2];
    const int*    rows = (const int*)d_in[3];
    const int*    cols = (const int*)d_in[4];
    const int*    uidx = (const int*)d_in[5];
    const int*    iidx = (const int*)d_in[6];
    float4*       out  = (float4*)d_out;

    const int B = 256;
    const int prepGrid  = (N_NODES * DH + B - 1) / B;   // 9375
    const int edgeGrid  = (N_EDGES + B - 1) / B;        // 7813
    const int scat4Grid = (N_EDGES / 4 + B - 1) / B;    // 1954
    const int nodeGrid  = (N_NODES + B - 1) / B;        // 1172

    // prologue
    prep_kernel<<<prepGrid, B>>>(uw, iw, rows, uidx, iidx, out);
    mark_nbr_kernel<<<edgeGrid, B>>>(rows, cols);
    scan_blocks_kernel<<<NBLK, SCAN_B>>>();
    scan_bsums_kernel<<<1, 512>>>();
    compact_kernel<<<nodeGrid, B>>>();
    scan_add_kernel<<<NBLK, SCAN_B>>>();
    scatter_kernel<<<scat4Grid, B>>>((const float4*)vals, (const int4*)rows,
                                     (const int4*)cols);

    // layer 1: A -> B (all rows)
    spmm_csr_kernel<0><<<SPMM_BLOCKS, B>>>();
    // layer 2: B -> A (active-list rows) + fused gather of layer-1 (bufB)
    spmm_list_kernel<1, 1><<<LIST_BLOCKS + GATHER_BLOCKS, B>>>(out);
    // layer 3: A -> B (sampled rows) + fused gather of layer-2 (bufA)
    spmm_sel_kernel<0, 0><<<SEL_BLOCKS + GATHER_BLOCKS, B>>>(out);
    // final gather of layer-3 (bufB)
    gather_kernel<1><<<GATHER_BLOCKS, B>>>(out);
}

// round 7
// speedup vs baseline: 1.1174x; 1.1174x over previous
#include <cuda_runtime.h>
#include <cuda_fp16.h>

// Problem constants (fixed by the reference setup_inputs)
constexpr int N_USERS = 200000;
constexpr int N_ITEMS = 100000;
constexpr int N_NODES = N_USERS + N_ITEMS;   // 300000
constexpr int N_EDGES = 2000000;
constexpr int N_IDX   = 16384;
constexpr int DH      = 8;                   // 64 halves = 8 uint4 (16B) per row
constexpr int N_SEL   = 2 * N_IDX;           // sampled-node list (with dups)

constexpr int SCAN_B  = 1024;
constexpr int NBLK    = (N_NODES + SCAN_B - 1) / SCAN_B;  // 293 (single wave)

// Allocation-free scratch (__device__ globals; zero-initialized at load)
__device__ uint4    g_bufA[(size_t)N_NODES * DH];   // 38.4 MB (fp16 rows)
__device__ uint4    g_bufB[(size_t)N_NODES * DH];   // 38.4 MB
__device__ int      g_cnt[N_NODES];                 // invariant: zero at launch entry
__device__ int      g_rowptr[N_NODES + 1];
__device__ int      g_cursor[N_NODES];
__device__ float2   g_edge[N_EDGES];                // {val, col-as-float-bits}, row-sorted
__device__ int      g_sel[N_SEL];                   // sampled nodes (dups ok)
__device__ unsigned g_state[NBLK];                  // lookback: aggr|FLAG (invariant: 0)
__device__ int      g_done;                         // finished-block counter (invariant: 0)

constexpr unsigned STATE_FLAG = 0x80000000u;

__device__ __forceinline__ uint4 pack8(const float* a) {
    uint4 r;
    half2 h0 = __floats2half2_rn(a[0], a[1]);
    half2 h1 = __floats2half2_rn(a[2], a[3]);
    half2 h2 = __floats2half2_rn(a[4], a[5]);
    half2 h3 = __floats2half2_rn(a[6], a[7]);
    r.x = *(const unsigned*)&h0; r.y = *(const unsigned*)&h1;
    r.z = *(const unsigned*)&h2; r.w = *(const unsigned*)&h3;
    return r;
}

__device__ __forceinline__ void unpack8(uint4 v, float* a) {
    float2 f0 = __half22float2(*(const half2*)&v.x);
    float2 f1 = __half22float2(*(const half2*)&v.y);
    float2 f2 = __half22float2(*(const half2*)&v.z);
    float2 f3 = __half22float2(*(const half2*)&v.w);
    a[0] = f0.x; a[1] = f0.y; a[2] = f1.x; a[3] = f1.y;
    a[4] = f2.x; a[5] = f2.y; a[6] = f3.x; a[7] = f3.y;
}

// ---------------------------------------------------------------------------
// prep: (a) bufA = fp16(concat(uw, iw)); (b) edge-row histogram
// (g_cnt zero on entry by invariant); (c) sel-list fill (dups allowed);
// (d) exact layer-0 output gather from fp32 weights.
__global__ void prep_kernel(const float4* __restrict__ uw,
                            const float4* __restrict__ iw,
                            const int* __restrict__ rows,
                            const int* __restrict__ uidx,
                            const int* __restrict__ iidx,
                            float4* __restrict__ out) {
    int t = blockIdx.x * blockDim.x + threadIdx.x;

    if (t < N_NODES * DH) {
        const float4* src = (t < N_USERS * DH) ? uw : iw;
        int idx2 = (t < N_USERS * DH) ? (t * 2) : ((t - N_USERS * DH) * 2);
        float4 a = __ldg(src + idx2);
        float4 b = __ldg(src + idx2 + 1);
        float f[8] = {a.x, a.y, a.z, a.w, b.x, b.y, b.z, b.w};
        g_bufA[t] = pack8(f);
    }
    if (t < N_EDGES) atomicAdd(&g_cnt[__ldg(rows + t)], 1);
    if (t < N_SEL) {
        g_sel[t] = (t < N_IDX) ? __ldg(uidx + t)
                               : (N_USERS + __ldg(iidx + (t - N_IDX)));
    }
    if (t < N_SEL * 16) {
        int row = t >> 4;
        int c   = t & 15;
        const float4* src;
        int node;
        if (row < N_IDX) { src = uw; node = __ldg(uidx + row); }
        else             { src = iw; node = __ldg(iidx + (row - N_IDX)); }
        float4 x = __ldg(src + (unsigned)node * 16 + c);
        out[t] = make_float4(0.25f * x.x, 0.25f * x.y, 0.25f * x.z, 0.25f * x.w);
    }
}

// ---------------------------------------------------------------------------
// Single-pass exclusive scan (decoupled lookback, all-aggregate variant).
// g_cnt -> g_rowptr & g_cursor. Also resets g_cnt (launch invariant) and
// self-cleans g_state/g_done via last-finisher election.
// Grid = NBLK (293) blocks of 1024: single wave, all blocks resident.
__global__ void __launch_bounds__(SCAN_B, 2) scan_kernel() {
    __shared__ int wsum[32];
    __shared__ int block_prefix;
    int i = blockIdx.x * SCAN_B + threadIdx.x;
    int v = (i < N_NODES) ? g_cnt[i] : 0;
    if (i < N_NODES) g_cnt[i] = 0;                  // restore invariant

    int lane = threadIdx.x & 31, wid = threadIdx.x >> 5;
    // warp-local inclusive scan
    int s = v;
    #pragma unroll
    for (int off = 1; off < 32; off <<= 1) {
        int n = __shfl_up_sync(0xffffffffu, s, off);
        if (lane >= off) s += n;
    }
    if (lane == 31) wsum[wid] = s;
    __syncthreads();
    if (wid == 0) {
        int ws = wsum[lane];
        #pragma unroll
        for (int off = 1; off < 32; off <<= 1) {
            int n = __shfl_up_sync(0xffffffffu, ws, off);
            if (lane >= off) ws += n;
        }
        wsum[lane] = ws;
    }
    __syncthreads();
    int incl = s + ((wid > 0) ? wsum[wid - 1] : 0);
    int aggr = wsum[31];                            // block total

    // publish aggregate immediately (before lookback: no deadlock)
    if (threadIdx.x == 0)
        atomicExch(&g_state[blockIdx.x], (unsigned)aggr | STATE_FLAG);

    // warp-0 lookback: sum ALL predecessor aggregates (lane-parallel)
    if (wid == 0) {
        int run = 0;
        for (int idx = (int)blockIdx.x - 1 - lane; idx >= 0; idx -= 32) {
            unsigned st;
            do { st = *((volatile unsigned*)&g_state[idx]); } while (!(st & STATE_FLAG));
            run += (int)(st & 0x7fffffffu);
        }
        #pragma unroll
        for (int off = 16; off > 0; off >>= 1)
            run += __shfl_down_sync(0xffffffffu, run, off);
        if (lane == 0) block_prefix = run;
    }
    __syncthreads();

    int ex = incl - v + block_prefix;               // global exclusive prefix
    if (i < N_NODES) { g_rowptr[i] = ex; g_cursor[i] = ex; }
    if (blockIdx.x == NBLK - 1 && threadIdx.x == SCAN_B - 1)
        g_rowptr[N_NODES] = N_EDGES;

    // last finisher resets lookback state (all blocks done reading by now)
    __syncthreads();
    if (threadIdx.x == 0) {
        __threadfence();
        if (atomicAdd(&g_done, 1) == NBLK - 1) {
            for (int k = 0; k < NBLK; k++) g_state[k] = 0;
            g_done = 0;
            __threadfence();
        }
    }
}

// scatter edges into row-sorted packed array
__global__ void scatter_kernel(const float* __restrict__ vals,
                               const int*   __restrict__ rows,
                               const int*   __restrict__ cols) {
    int e = blockIdx.x * blockDim.x + threadIdx.x;
    if (e >= N_EDGES) return;
    int r   = __ldg(rows + e);
    int pos = atomicAdd(&g_cursor[r], 1);
    g_edge[pos] = make_float2(__ldg(vals + e), __int_as_float(__ldg(cols + e)));
}

// ---------------------------------------------------------------------------
// Row body: direct per-thread CSR loop, chunk-4 with zero-padding.
// 8 threads per row (c = lane&7). Per chunk: 4 independent edge loads
// (broadcast across the 8 lanes -> 1 sector each), then 4 independent
// gathers in flight. Padded slots use v=0/col=0 (hot L1 line, branchless).
__device__ __forceinline__ void spmm_row(const uint4* __restrict__ cur,
                                         uint4* __restrict__ nxt,
                                         int row, int c) {
    int beg = __ldg(&g_rowptr[row]);
    int end = __ldg(&g_rowptr[row + 1]);

    float acc[8] = {0.f, 0.f, 0.f, 0.f, 0.f, 0.f, 0.f, 0.f};
    for (int base = beg; base < end; base += 4) {
        float2 ev[4];
        #pragma unroll
        for (int k = 0; k < 4; k++) {
            int idx = base + k;
            ev[k] = (idx < end) ? __ldg((const float2*)g_edge + idx)
                                : make_float2(0.f, __int_as_float(0));
        }
        uint4 p[4];
        #pragma unroll
        for (int k = 0; k < 4; k++)
            p[k] = __ldg(cur + (unsigned)__float_as_int(ev[k].y) * DH + c);
        #pragma unroll
        for (int k = 0; k < 4; k++) {
            float x[8];
            unpack8(p[k], x);
            #pragma unroll
            for (int j = 0; j < 8; j++) acc[j] += ev[k].x * x[j];
        }
    }
    nxt[(unsigned)row * DH + c] = pack8(acc);
}

// Fused gather tail: out += 0.25 * buf16[sampled]  (8 threads/sampled row)
__device__ __forceinline__ void gather_body(const uint4* __restrict__ buf,
                                            float4* __restrict__ out, int t) {
    int row = t >> 3;
    int c   = t & 7;
    int node = g_sel[row];
    float x[8];
    unpack8(__ldg(buf + (unsigned)node * DH + c), x);
    float4* o = out + (unsigned)row * 16 + c * 2;
    float4 p0 = o[0], p1 = o[1];
    o[0] = make_float4(p0.x + 0.25f * x[0], p0.y + 0.25f * x[1],
                       p0.z + 0.25f * x[2], p0.w + 0.25f * x[3]);
    o[1] = make_float4(p1.x + 0.25f * x[4], p1.y + 0.25f * x[5],
                       p1.z + 0.25f * x[6], p1.w + 0.25f * x[7]);
}

constexpr int SPMM_BLOCKS   = (N_NODES * DH) / 256;          // 9375
constexpr int GATHER_BLOCKS = (N_SEL * DH) / 256;            // 1024
constexpr int SEL_BLOCKS    = (N_SEL * DH) / 256;            // 1024

// Full SpMM over all rows. DIR=0: A->B, DIR=1: B->A.
// GPREV: -1 = no fused gather; else gather from buf GPREV (0=A,1=B) into out.
template <int DIR, int GPREV>
__global__ void spmm_csr_kernel(float4* __restrict__ out) {
    const uint4* __restrict__ cur = DIR ? g_bufB : g_bufA;
    uint4*       __restrict__ nxt = DIR ? g_bufA : g_bufB;
    int b = blockIdx.x;
    if (b < SPMM_BLOCKS) {
        int t = b * blockDim.x + threadIdx.x;
        spmm_row(cur, nxt, t >> 3, t & 7);
    } else if (GPREV >= 0) {
        int t = (b - SPMM_BLOCKS) * blockDim.x + threadIdx.x;
        gather_body(GPREV ? g_bufB : g_bufA, out, t);
    }
}

// Selective SpMM over sampled rows (dups benign: identical values written).
// Fused gather of the previous layer (GPREV buffer) in tail blocks.
template <int DIR, int GPREV>
__global__ void spmm_sel_kernel(float4* __restrict__ out) {
    const uint4* __restrict__ cur = DIR ? g_bufB : g_bufA;
    uint4*       __restrict__ nxt = DIR ? g_bufA : g_bufB;
    int b = blockIdx.x;
    if (b < SEL_BLOCKS) {
        int t = b * blockDim.x + threadIdx.x;
        spmm_row(cur, nxt, g_sel[t >> 3], t & 7);
    } else {
        int t = (b - SEL_BLOCKS) * blockDim.x + threadIdx.x;
        gather_body(GPREV ? g_bufB : g_bufA, out, t);
    }
}

// Final standalone gather (layer 3 result)
template <int W>
__global__ void gather_kernel(float4* __restrict__ out) {
    int t = blockIdx.x * blockDim.x + threadIdx.x;
    gather_body(W ? g_bufB : g_bufA, out, t);
}

extern "C" void kernel_launch(void* const* d_in, const int* in_sizes, int n_in,
                              void* d_out, int out_size) {
    const float4* uw   = (const float4*)d_in[0];
    const float4* iw   = (const float4*)d_in[1];
    const float*  vals = (const float*)d_in[2];
    const int*    rows = (const int*)d_in[3];
    const int*    cols = (const int*)d_in[4];
    const int*    uidx = (const int*)d_in[5];
    const int*    iidx = (const int*)d_in[6];
    float4*       out  = (float4*)d_out;

    const int B = 256;
    const int prepGrid = (N_NODES * DH + B - 1) / B;   // 9375 (covers all fused jobs)
    const int edgeGrid = (N_EDGES + B - 1) / B;        // 7813

    // prologue: fp16 convert + histogram + sel list + exact layer-0 gather
    prep_kernel<<<prepGrid, B>>>(uw, iw, rows, uidx, iidx, out);
    // single-pass scan (replaces 3 scan kernels)
    scan_kernel<<<NBLK, SCAN_B>>>();
    scatter_kernel<<<edgeGrid, B>>>(vals, rows, cols);

    // layer 1: A -> B (all rows)
    spmm_csr_kernel<0, -1><<<SPMM_BLOCKS, B>>>(out);
    // layer 2: B -> A (all rows) + fused gather of layer-1 (bufB)
    spmm_csr_kernel<1, 1><<<SPMM_BLOCKS + GATHER_BLOCKS, B>>>(out);
    // layer 3: A -> B (sampled rows) + fused gather of layer-2 (bufA)
    spmm_sel_kernel<0, 0><<<SEL_BLOCKS + GATHER_BLOCKS, B>>>(out);
    // final gather of layer-3 (bufB)
    gather_kernel<1><<<GATHER_BLOCKS, B>>>(out);
}